// round 2
// baseline (speedup 1.0000x reference)
#include <cuda_runtime.h>
#include <math.h>

#define SR          44100.0
#define N_SAMPLES   131072
#define N_GRAINS    512
#define GRAIN_N     4096
#define BATCH       32
#define LOG2_F0_MIN 8.0f      /* log2(256) */
#define LOG2_F0_MAX 13.0f     /* log2(8192) */
#define TYP_SLOPE   14.35546875f  /* 44100/(12*256) */
#define PI_F        3.14159265358979323846f
#define TWO_PI_F    6.28318530717958647692f

// ---- scratch (no allocations allowed) ----
__device__ double g_S0[BATCH * 128];         // S[t] for t in [0,128) per batch
__device__ double g_rq[BATCH * 2];           // recurrence: S[t+128] = r*S[t] + q
__device__ double g_f0s[BATCH * N_GRAINS];   // f0/SR per grain (double)
__device__ float  g_coeff[BATCH * N_GRAINS]; // amp_norm / sqrt(f0)
__device__ float  g_window[GRAIN_N];         // sin^2(pi t / GRAIN_N)
__device__ float  g_inv[BATCH];              // 1/||x||

// ============================================================
// Kernel 1: per-batch prep. 32 blocks x 512 threads.
//  S[t] = exp(-2048a) * expm1(a*(t+1)) / expm1(a),  a = gamma*ln2/SR
//  (closed form of the reference's cumsum of f0*2^(gamma*support)/SR,
//   with the grain-independent part factored out)
// ============================================================
__global__ void prep_kernel(const float* __restrict__ theta_d,
                            const float* __restrict__ theta_s,
                            const float* __restrict__ log2_f0_u) {
    const int b   = blockIdx.x;
    const int tid = threadIdx.x;

    const float d     = theta_d[b];
    const float slope = theta_s[b] * 2.0f - 1.0f;

    // gamma in fp32 to track the reference's fp32 value
    const float gamma_f = tanf(0.95f * slope * (PI_F * 0.5f)) * TYP_SLOPE * 0.25f;
    const double a = (double)gamma_f * 0.6931471805599453 / SR;

    if (tid < 128) {
        if (a == 0.0) {
            g_S0[b * 128 + tid] = (double)(tid + 1);
        } else {
            const double pref  = exp(-2048.0 * a);
            const double denom = expm1(a);
            g_S0[b * 128 + tid] = pref * expm1(a * (double)(tid + 1)) / denom;
        }
    }
    if (tid == 0) {
        if (a == 0.0) {
            g_rq[b * 2 + 0] = 1.0;
            g_rq[b * 2 + 1] = 128.0;
        } else {
            const double pref  = exp(-2048.0 * a);
            const double denom = expm1(a);
            const double r     = exp(128.0 * a);
            g_rq[b * 2 + 0] = r;
            g_rq[b * 2 + 1] = pref * (r - 1.0) / denom;
        }
    }

    // ---- per-grain quantities ----
    const float offset = 0.25f * d + 0.75f * d * d;
    const float so0  = (1.0f - d) * (float)N_GRAINS * (0.0f - offset);
    const float amp0 = 1.0f / (1.0f + expf(2.0f * so0));   // max amp (g=0)

    for (int g = tid; g < N_GRAINS; g += blockDim.x) {
        const int idx = b * N_GRAINS + g;
        const float u  = log2_f0_u[idx];
        const float f0 = exp2f(u * (LOG2_F0_MAX - LOG2_F0_MIN) + LOG2_F0_MIN);
        const float so = (1.0f - d) * (float)N_GRAINS * ((float)g / (float)N_GRAINS - offset);
        const float amp = 1.0f / (1.0f + expf(2.0f * so));
        g_coeff[idx] = (amp / amp0) / sqrtf(f0);
        g_f0s[idx]   = (double)f0 / SR;
    }

    if (b == 0) {
        for (int t = tid; t < GRAIN_N; t += blockDim.x) {
            const float w = sinpif((float)t / (float)GRAIN_N);
            g_window[t] = w * w;
        }
    }
}

// ============================================================
// Kernel 2: synth + scatter. grid (512, 32), 128 threads.
// One block per (grain, batch). onset+t never wraps (onset < N-GRAIN_N).
// Per-thread fp64 recurrence replaces the S-table load.
// ============================================================
__global__ void __launch_bounds__(128)
synth_kernel(const int* __restrict__ onsets, float* __restrict__ out) {
    const int g = blockIdx.x;
    const int b = blockIdx.y;
    const int idx = b * N_GRAINS + g;

    const int    onset = onsets[idx];
    const float  coeff = g_coeff[idx];
    const double f0s   = g_f0s[idx];
    const double r     = g_rq[b * 2 + 0];
    const double q     = g_rq[b * 2 + 1];
    double S           = g_S0[b * 128 + threadIdx.x];

    float* __restrict__ row = out + (size_t)b * N_SAMPLES + onset;

    #pragma unroll 4
    for (int t = threadIdx.x; t < GRAIN_N; t += 128) {
        const double y  = f0s * S;              // phase in cycles
        const double fr = y - rint(y);          // [-0.5, 0.5]
        const float  s  = __sinf((float)fr * TWO_PI_F);
        const float  v  = s * coeff * g_window[t];
        atomicAdd(row + t, v);
        S = fma(r, S, q);                       // S[t+128]
    }
}

// ============================================================
// Kernel 3: per-batch L2 norm. 32 blocks x 256 threads.
// ============================================================
__global__ void norm_kernel(const float* __restrict__ out) {
    const int b   = blockIdx.x;
    const int tid = threadIdx.x;
    const float* __restrict__ row = out + (size_t)b * N_SAMPLES;

    double s = 0.0;
    for (int i = tid; i < N_SAMPLES; i += 256) {
        const double v = (double)row[i];
        s += v * v;
    }
    __shared__ double sh[8];
    for (int off = 16; off > 0; off >>= 1)
        s += __shfl_down_sync(0xFFFFFFFFu, s, off);
    if ((tid & 31) == 0) sh[tid >> 5] = s;
    __syncthreads();
    if (tid < 8) {
        s = sh[tid];
        for (int off = 4; off > 0; off >>= 1)
            s += __shfl_down_sync(0xFFu, s, off);
        if (tid == 0) g_inv[b] = (float)(1.0 / sqrt(s));
    }
}

// ============================================================
// Kernel 4: scale by 1/norm.
// ============================================================
__global__ void scale_kernel(float* __restrict__ out) {
    const int i = blockIdx.x * blockDim.x + threadIdx.x;
    if (i < BATCH * N_SAMPLES) {
        out[i] *= g_inv[i >> 17];   // N_SAMPLES = 2^17
    }
}

extern "C" void kernel_launch(void* const* d_in, const int* in_sizes, int n_in,
                              void* d_out, int out_size) {
    const float* theta_d = (const float*)d_in[0];
    const float* theta_s = (const float*)d_in[1];
    const float* u       = (const float*)d_in[2];
    const int*   onsets  = (const int*)d_in[3];
    float* out = (float*)d_out;

    cudaMemsetAsync(out, 0, (size_t)BATCH * N_SAMPLES * sizeof(float));

    prep_kernel<<<BATCH, 512>>>(theta_d, theta_s, u);

    dim3 grid(N_GRAINS, BATCH);
    synth_kernel<<<grid, 128>>>(onsets, out);

    norm_kernel<<<BATCH, 256>>>(out);

    const int total = BATCH * N_SAMPLES;
    scale_kernel<<<(total + 255) / 256, 256>>>(out);
}

// round 5
// speedup vs baseline: 1.4444x; 1.4444x over previous
#include <cuda_runtime.h>
#include <math.h>

#define SR          44100.0
#define N_SAMPLES   131072
#define N_GRAINS    512
#define GRAIN_N     4096
#define BATCH       32
#define LOG2_F0_MIN 8.0f      /* log2(256) */
#define LOG2_F0_MAX 13.0f     /* log2(8192) */
#define TYP_SLOPE   14.35546875f  /* 44100/(12*256) */
#define PI_F        3.14159265358979323846f
#define TWO_PI_F    6.28318530717958647692f

// ---- scratch (no allocations allowed) ----
__device__ double g_S0[BATCH * 128];         // S[t], t in [0,128), per batch
__device__ double g_rq[BATCH * 2];           // S[t+128] = r*S[t] + q
__device__ double g_f0s[BATCH * N_GRAINS];   // f0/SR per grain
__device__ float  g_coeff[BATCH * N_GRAINS]; // amp_norm / sqrt(f0)
__device__ float  g_window[GRAIN_N];         // sin^2(pi t / GRAIN_N)
__device__ double g_sum[BATCH];              // ||x||^2 accumulator

// ============================================================
// Kernel 1: per-batch prep. 32 blocks x 512 threads.
//  S[t] = exp(-2048a)*expm1(a(t+1))/expm1(a),  a = gamma*ln2/SR
//  (exact closed form of the reference's cumsum, grain part factored out)
// ============================================================
__global__ void prep_kernel(const float* __restrict__ theta_d,
                            const float* __restrict__ theta_s,
                            const float* __restrict__ log2_f0_u) {
    const int b   = blockIdx.x;
    const int tid = threadIdx.x;

    const float d     = theta_d[b];
    const float slope = theta_s[b] * 2.0f - 1.0f;

    // gamma in fp32 to track the reference's fp32 value
    const float gamma_f = tanf(0.95f * slope * (PI_F * 0.5f)) * TYP_SLOPE * 0.25f;
    const double a = (double)gamma_f * 0.6931471805599453 / SR;

    if (tid < 128) {
        if (a == 0.0) {
            g_S0[b * 128 + tid] = (double)(tid + 1);
        } else {
            const double pref  = exp(-2048.0 * a);
            const double denom = expm1(a);
            g_S0[b * 128 + tid] = pref * expm1(a * (double)(tid + 1)) / denom;
        }
    }
    if (tid == 0) {
        if (a == 0.0) {
            g_rq[b * 2 + 0] = 1.0;
            g_rq[b * 2 + 1] = 128.0;
        } else {
            const double pref  = exp(-2048.0 * a);
            const double denom = expm1(a);
            const double r     = exp(128.0 * a);
            g_rq[b * 2 + 0] = r;
            g_rq[b * 2 + 1] = pref * (r - 1.0) / denom;
        }
        g_sum[b] = 0.0;   // re-zero every replay
    }

    // ---- per-grain quantities ----
    const float offset = 0.25f * d + 0.75f * d * d;
    const float so0  = (1.0f - d) * (float)N_GRAINS * (0.0f - offset);
    const float amp0 = 1.0f / (1.0f + expf(2.0f * so0));   // max amp (g=0)

    for (int g = tid; g < N_GRAINS; g += blockDim.x) {
        const int idx = b * N_GRAINS + g;
        const float u  = log2_f0_u[idx];
        const float f0 = exp2f(u * (LOG2_F0_MAX - LOG2_F0_MIN) + LOG2_F0_MIN);
        const float so = (1.0f - d) * (float)N_GRAINS * ((float)g / (float)N_GRAINS - offset);
        const float amp = 1.0f / (1.0f + expf(2.0f * so));
        g_coeff[idx] = (amp / amp0) / sqrtf(f0);
        g_f0s[idx]   = (double)f0 / SR;
    }

    if (b == 0) {
        for (int t = tid; t < GRAIN_N; t += blockDim.x) {
            const float w = sinpif((float)t / (float)GRAIN_N);
            g_window[t] = w * w;
        }
    }
}

// ============================================================
// Kernel 2: synth + scatter. grid (512, 32), 128 threads.
// One block per (grain, batch). onset+t never wraps.
// Phase carried directly: P[t+128] = r*P[t] + f0s*q
// Inner loop: 3 fp64 ops (DRND, DADD, DFMA) + sin + RED.
// ============================================================
__global__ void __launch_bounds__(128)
synth_kernel(const int* __restrict__ onsets, float* __restrict__ out) {
    const int g = blockIdx.x;
    const int b = blockIdx.y;
    const int idx = b * N_GRAINS + g;

    const int    onset = onsets[idx];
    const float  coeff = g_coeff[idx];
    const double f0s   = g_f0s[idx];
    const double r     = g_rq[b * 2 + 0];
    const double qq    = f0s * g_rq[b * 2 + 1];
    double P           = f0s * g_S0[b * 128 + threadIdx.x];  // phase in cycles

    float* __restrict__ row = out + (size_t)b * N_SAMPLES + onset;

    #pragma unroll 8
    for (int t = threadIdx.x; t < GRAIN_N; t += 128) {
        const double fr = P - rint(P);          // [-0.5, 0.5] cycles
        const float  s  = __sinf((float)fr * TWO_PI_F);
        const float  v  = s * coeff * g_window[t];
        atomicAdd(row + t, v);                  // compiles to RED (no return)
        P = fma(r, P, qq);
    }
}

// ============================================================
// Kernel 3: norm^2. 2048 blocks (64/batch) x 256 threads, float4.
// Per-block partial -> one double atomicAdd per block.
// ============================================================
__global__ void __launch_bounds__(256)
norm_kernel(const float4* __restrict__ out4) {
    const int b     = blockIdx.x >> 6;          // 64 blocks per batch
    const int slice = blockIdx.x & 63;
    const int tid   = threadIdx.x;
    // each batch: 32768 float4; each block: 512 float4; each thread: 2
    const float4* __restrict__ base = out4 + (size_t)b * 32768 + slice * 512;

    float s = 0.0f;
    #pragma unroll
    for (int k = 0; k < 2; k++) {
        const float4 v = base[tid + 256 * k];
        s += v.x * v.x + v.y * v.y + v.z * v.z + v.w * v.w;
    }
    // block reduce
    __shared__ float sh[8];
    for (int off = 16; off > 0; off >>= 1)
        s += __shfl_down_sync(0xFFFFFFFFu, s, off);
    if ((tid & 31) == 0) sh[tid >> 5] = s;
    __syncthreads();
    if (tid < 8) {
        s = sh[tid];
        for (int off = 4; off > 0; off >>= 1)
            s += __shfl_down_sync(0xFFu, s, off);
        if (tid == 0) atomicAdd(&g_sum[b], (double)s);
    }
}

// ============================================================
// Kernel 4: scale by 1/norm. 4096 blocks x 256 threads, float4.
// Each block covers one batch's slice; finalizes inv once per block.
// ============================================================
__global__ void __launch_bounds__(256)
scale_kernel(float4* __restrict__ out4) {
    const int i = blockIdx.x * 256 + threadIdx.x;   // float4 index
    const int b = i >> 15;                          // 32768 float4 per batch

    __shared__ float sinv;
    if (threadIdx.x == 0) sinv = (float)(1.0 / sqrt(g_sum[b]));
    __syncthreads();
    const float inv = sinv;

    float4 v = out4[i];
    v.x *= inv; v.y *= inv; v.z *= inv; v.w *= inv;
    out4[i] = v;
}

extern "C" void kernel_launch(void* const* d_in, const int* in_sizes, int n_in,
                              void* d_out, int out_size) {
    const float* theta_d = (const float*)d_in[0];
    const float* theta_s = (const float*)d_in[1];
    const float* u       = (const float*)d_in[2];
    const int*   onsets  = (const int*)d_in[3];
    float* out = (float*)d_out;

    cudaMemsetAsync(out, 0, (size_t)BATCH * N_SAMPLES * sizeof(float));

    prep_kernel<<<BATCH, 512>>>(theta_d, theta_s, u);

    dim3 grid(N_GRAINS, BATCH);
    synth_kernel<<<grid, 128>>>(onsets, out);

    norm_kernel<<<2048, 256>>>((const float4*)out);

    scale_kernel<<<4096, 256>>>((float4*)out);
}